// round 4
// baseline (speedup 1.0000x reference)
#include <cuda_runtime.h>
#include <cuda_bf16.h>
#include <math.h>

#define N 8192
#define EPS 1e-5f
#define FACT 2.0f
#define PD_EPS 1e-6f
#define CUTOFF 25.0f

#define RW 4                   // rows per work unit (one warp per unit)
#define UNITS (N / RW)         // 2048
#define CTAS 296
#define TPB 128
#define NWARPS (CTAS * TPB / 32)  // 1184

__device__ float4 g_p2[N];     // packed {x, y, z, -0.5*(x^2+y^2+z^2)}
__device__ float g_pd[N];      // per-row pairwise distance
__device__ int g_ctr;          // work-steal counter

// ---------- packed f32x2 helpers (sm_100+) ----------
typedef unsigned long long ull;
__device__ __forceinline__ ull pk2(float lo, float hi) {
    ull d; asm("mov.b64 %0, {%1, %2};" : "=l"(d) : "f"(lo), "f"(hi)); return d;
}
__device__ __forceinline__ ull ffma2(ull a, ull b, ull c) {
    ull d; asm("fma.rn.f32x2 %0, %1, %2, %3;" : "=l"(d) : "l"(a), "l"(b), "l"(c)); return d;
}
__device__ __forceinline__ void upk2(ull v, float& lo, float& hi) {
    asm("mov.b64 {%0, %1}, %2;" : "=f"(lo), "=f"(hi) : "l"(v));
}

// ---------- prep: pack pc2, seed counter ----------
__global__ void prep_kernel(const float* __restrict__ pc2) {
    int j = blockIdx.x * blockDim.x + threadIdx.x;
    if (j == 0) g_ctr = NWARPS;   // first NWARPS units assigned statically
    if (j < N) {
        float x = pc2[j], y = pc2[N + j], z = pc2[2 * N + j];
        g_p2[j] = make_float4(x, y, z, -0.5f * fmaf(x, x, fmaf(y, y, z * z)));
    }
}

// ---------- main: persistent warps, two-pass soft-knn per 4-row unit ----------
__global__ __launch_bounds__(TPB, 4)
void soft_knn_kernel(const float* __restrict__ pc1, float* __restrict__ out) {
    const int lane = threadIdx.x & 31;
    const float4* __restrict__ p2 = g_p2;

    int u = (blockIdx.x * TPB + threadIdx.x) >> 5;   // global warp id = first unit

    while (u < UNITS) {
        const int row0 = u * RW;

        // Load the 4 query rows; pack into 2 f32x2 pairs.
        float x1s[RW], y1s[RW], z1s[RW], s1[RW];
#pragma unroll
        for (int r = 0; r < RW; r++) {
            int i = row0 + r;
            x1s[r] = pc1[i];
            y1s[r] = pc1[N + i];
            z1s[r] = pc1[2 * N + i];
            s1[r] = fmaf(x1s[r], x1s[r], fmaf(y1s[r], y1s[r], z1s[r] * z1s[r]));
        }
        ull x1[RW / 2], y1[RW / 2], z1[RW / 2];
#pragma unroll
        for (int q = 0; q < RW / 2; q++) {
            x1[q] = pk2(x1s[2 * q], x1s[2 * q + 1]);
            y1[q] = pk2(y1s[2 * q], y1s[2 * q + 1]);
            z1[q] = pk2(z1s[2 * q], z1s[2 * q + 1]);
        }

        // ---- Pass 1: hmax[r] = max_j ( dot - 0.5*|p2_j|^2 )  (<=> min d2) ----
        float hmax[RW];
#pragma unroll
        for (int r = 0; r < RW; r++) hmax[r] = -3.4e38f;

        for (int j = lane; j < N; j += 32) {
            float4 p = p2[j];
            ull px = pk2(p.x, p.x), py = pk2(p.y, p.y), pz = pk2(p.z, p.z), pw = pk2(p.w, p.w);
#pragma unroll
            for (int q = 0; q < RW / 2; q++) {
                ull t = ffma2(z1[q], pz, pw);
                t = ffma2(y1[q], py, t);
                t = ffma2(x1[q], px, t);
                float h0, h1; upk2(t, h0, h1);
                hmax[2 * q]     = fmaxf(hmax[2 * q], h0);
                hmax[2 * q + 1] = fmaxf(hmax[2 * q + 1], h1);
            }
        }
#pragma unroll
        for (int r = 0; r < RW; r++) {
#pragma unroll
            for (int ofs = 16; ofs > 0; ofs >>= 1)
                hmax[r] = fmaxf(hmax[r], __shfl_xor_sync(0xFFFFFFFFu, hmax[r], ofs));
        }

        // Thresholds. hth clamped to hmax -> argmax point ALWAYS qualifies
        // (identical FMA chain in pass 2 reproduces h == hmax bitwise).
        float m[RW], hth[RW];
#pragma unroll
        for (int r = 0; r < RW; r++) {
            float mind2 = fmaf(-2.0f, hmax[r], s1[r]);
            float mm = FACT / fmaxf(mind2, EPS);
            m[r] = mm;
            float t = (mm > CUTOFF) ? 0.5f * (s1[r] - FACT / (mm - CUTOFF)) : -3.4e38f;
            hth[r] = fminf(t, hmax[r]);
        }

        // ---- Pass 2: softmax-weighted accumulation; one branch region/iter ----
        float sw[RW], ax[RW], ay[RW], az[RW];
#pragma unroll
        for (int r = 0; r < RW; r++) { sw[r] = 0.f; ax[r] = 0.f; ay[r] = 0.f; az[r] = 0.f; }

        for (int j = lane; j < N; j += 32) {
            float4 p = p2[j];
            ull px = pk2(p.x, p.x), py = pk2(p.y, p.y), pz = pk2(p.z, p.z), pw = pk2(p.w, p.w);
            float h[RW];
#pragma unroll
            for (int q = 0; q < RW / 2; q++) {
                ull t = ffma2(z1[q], pz, pw);
                t = ffma2(y1[q], py, t);
                t = ffma2(x1[q], px, t);
                upk2(t, h[2 * q], h[2 * q + 1]);
            }
            float g0 = fmaxf(h[0] - hth[0], h[1] - hth[1]);
            float g1 = fmaxf(h[2] - hth[2], h[3] - hth[3]);
            if (fmaxf(g0, g1) >= 0.0f) {   // rare: only near-NN points
#pragma unroll
                for (int r = 0; r < RW; r++) {
                    if (h[r] >= hth[r]) {
                        float d2 = fmaf(-2.0f, h[r], s1[r]);
                        float arg = FACT / fmaxf(d2, EPS);
                        float w = __expf(arg - m[r]);
                        sw[r] += w;
                        ax[r] = fmaf(w, p.x, ax[r]);
                        ay[r] = fmaf(w, p.y, ay[r]);
                        az[r] = fmaf(w, p.z, az[r]);
                    }
                }
            }
        }

        // Warp butterfly reductions (all lanes end with totals)
#pragma unroll
        for (int r = 0; r < RW; r++) {
#pragma unroll
            for (int ofs = 16; ofs > 0; ofs >>= 1) {
                sw[r] += __shfl_xor_sync(0xFFFFFFFFu, sw[r], ofs);
                ax[r] += __shfl_xor_sync(0xFFFFFFFFu, ax[r], ofs);
                ay[r] += __shfl_xor_sync(0xFFFFFFFFu, ay[r], ofs);
                az[r] += __shfl_xor_sync(0xFFFFFFFFu, az[r], ofs);
            }
        }

        if (lane < RW) {
            int r = lane;
            int i = row0 + r;
            float inv = 1.0f / sw[r];
            float px = ax[r] * inv, py = ay[r] * inv, pz = az[r] * inv;
            out[i] = px;
            out[N + i] = py;
            out[2 * N + i] = pz;
            float dx = x1s[r] - px + PD_EPS;
            float dy = y1s[r] - py + PD_EPS;
            float dz = z1s[r] - pz + PD_EPS;
            g_pd[i] = sqrtf(fmaf(dx, dx, fmaf(dy, dy, dz * dz)));
        }

        // Steal next unit
        if (lane == 0) u = atomicAdd(&g_ctr, 1);
        u = __shfl_sync(0xFFFFFFFFu, u, 0);
    }
}

// ---------- deterministic fixed-order mean ----------
__global__ void mean_kernel(float* __restrict__ out, int out_size) {
    __shared__ float ss[32];
    const int tid = threadIdx.x;
    float acc = 0.f;
    for (int i = tid; i < N; i += 1024) acc += g_pd[i];
#pragma unroll
    for (int ofs = 16; ofs > 0; ofs >>= 1)
        acc += __shfl_xor_sync(0xFFFFFFFFu, acc, ofs);
    if ((tid & 31) == 0) ss[tid >> 5] = acc;
    __syncthreads();
    if (tid < 32) {
        float a = ss[tid];
#pragma unroll
        for (int ofs = 16; ofs > 0; ofs >>= 1)
            a += __shfl_xor_sync(0xFFFFFFFFu, a, ofs);
        if (tid == 0 && out_size > 3 * N) out[3 * N] = a * (1.0f / N);
    }
}

extern "C" void kernel_launch(void* const* d_in, const int* in_sizes, int n_in,
                              void* d_out, int out_size) {
    const float* pc1 = (const float*)d_in[0];
    const float* pc2 = (const float*)d_in[1];
    float* out = (float*)d_out;

    prep_kernel<<<(N + 255) / 256, 256>>>(pc2);
    soft_knn_kernel<<<CTAS, TPB>>>(pc1, out);
    mean_kernel<<<1, 1024>>>(out, out_size);
}

// round 5
// speedup vs baseline: 1.5066x; 1.5066x over previous
#include <cuda_runtime.h>
#include <cuda_bf16.h>
#include <math.h>

#define N 8192
#define EPS 1e-5f
#define FACT 2.0f
#define PD_EPS 1e-6f
#define CUTOFF 25.0f

#define RW 2                       // rows per work unit (one warp per unit)
#define UNITS (N / RW)             // 4096
#define CTAS 296                   // 2 CTAs/SM on 148 SMs
#define TPB 256                    // 8 warps/CTA -> 16 warps/SM, 4/SMSP
#define NWARPS (CTAS * TPB / 32)   // 2368

__device__ float4 g_p2[N];   // packed {x, y, z, -0.5*(x^2+y^2+z^2)}
__device__ float g_pd[N];    // per-row pairwise distance
__device__ int g_ctr;        // work-steal counter

// h = dot(p1, p2_j) - 0.5*|p2_j|^2   (argmax h == argmin d2; d2 = s1 - 2h)
__device__ __forceinline__ float hdot(float x, float y, float z, float4 p) {
    return fmaf(x, p.x, fmaf(y, p.y, fmaf(z, p.z, p.w)));
}

__global__ void prep_kernel(const float* __restrict__ pc2) {
    int j = blockIdx.x * blockDim.x + threadIdx.x;
    if (j == 0) g_ctr = NWARPS;   // first NWARPS units assigned statically
    if (j < N) {
        float x = pc2[j], y = pc2[N + j], z = pc2[2 * N + j];
        g_p2[j] = make_float4(x, y, z, -0.5f * fmaf(x, x, fmaf(y, y, z * z)));
    }
}

__global__ __launch_bounds__(TPB)
void soft_knn_kernel(const float* __restrict__ pc1, float* __restrict__ out) {
    const int lane = threadIdx.x & 31;
    const float4* __restrict__ p2 = g_p2;

    int u = (blockIdx.x * TPB + threadIdx.x) >> 5;   // global warp id = first unit

    while (u < UNITS) {
        const int row0 = u * RW;

        float x0 = pc1[row0],     y0 = pc1[N + row0],     z0 = pc1[2 * N + row0];
        float x1 = pc1[row0 + 1], y1 = pc1[N + row0 + 1], z1 = pc1[2 * N + row0 + 1];
        float s0 = fmaf(x0, x0, fmaf(y0, y0, z0 * z0));
        float s1 = fmaf(x1, x1, fmaf(y1, y1, z1 * z1));

        // ---- Pass 1: hmax per row (j unrolled x4, loads front-batched) ----
        float hm0 = -3.4e38f, hm1 = -3.4e38f;
        for (int j = lane; j < N; j += 128) {
            float4 pa = p2[j];
            float4 pb = p2[j + 32];
            float4 pc = p2[j + 64];
            float4 pd = p2[j + 96];
            hm0 = fmaxf(hm0, fmaxf(fmaxf(hdot(x0, y0, z0, pa), hdot(x0, y0, z0, pb)),
                                   fmaxf(hdot(x0, y0, z0, pc), hdot(x0, y0, z0, pd))));
            hm1 = fmaxf(hm1, fmaxf(fmaxf(hdot(x1, y1, z1, pa), hdot(x1, y1, z1, pb)),
                                   fmaxf(hdot(x1, y1, z1, pc), hdot(x1, y1, z1, pd))));
        }
#pragma unroll
        for (int ofs = 16; ofs > 0; ofs >>= 1) {
            hm0 = fmaxf(hm0, __shfl_xor_sync(0xFFFFFFFFu, hm0, ofs));
            hm1 = fmaxf(hm1, __shfl_xor_sync(0xFFFFFFFFu, hm1, ofs));
        }

        // Thresholds; clamp to hmax so the argmax point ALWAYS qualifies
        // (identical fmaf chain in pass 2 reproduces h == hmax bitwise).
        float mind0 = fmaf(-2.0f, hm0, s0), mind1 = fmaf(-2.0f, hm1, s1);
        float m0 = FACT / fmaxf(mind0, EPS), m1 = FACT / fmaxf(mind1, EPS);
        float t0 = (m0 > CUTOFF) ? 0.5f * (s0 - FACT / (m0 - CUTOFF)) : -3.4e38f;
        float t1 = (m1 > CUTOFF) ? 0.5f * (s1 - FACT / (m1 - CUTOFF)) : -3.4e38f;
        float hth0 = fminf(t0, hm0), hth1 = fminf(t1, hm1);

        // ---- Pass 2: one gate per 4 j's; exp only where mass is non-negligible ----
        float sw0 = 0.f, ax0 = 0.f, ay0 = 0.f, az0 = 0.f;
        float sw1 = 0.f, ax1 = 0.f, ay1 = 0.f, az1 = 0.f;
        for (int j = lane; j < N; j += 128) {
            float4 pa = p2[j];
            float4 pb = p2[j + 32];
            float4 pc = p2[j + 64];
            float4 pd = p2[j + 96];
            float h0a = hdot(x0, y0, z0, pa), h0b = hdot(x0, y0, z0, pb);
            float h0c = hdot(x0, y0, z0, pc), h0d = hdot(x0, y0, z0, pd);
            float h1a = hdot(x1, y1, z1, pa), h1b = hdot(x1, y1, z1, pb);
            float h1c = hdot(x1, y1, z1, pc), h1d = hdot(x1, y1, z1, pd);
            float r0 = fmaxf(fmaxf(h0a, h0b), fmaxf(h0c, h0d));
            float r1 = fmaxf(fmaxf(h1a, h1b), fmaxf(h1c, h1d));
            if (r0 >= hth0 || r1 >= hth1) {   // rare: near-NN candidates only
                float hs0[4] = {h0a, h0b, h0c, h0d};
                float hs1[4] = {h1a, h1b, h1c, h1d};
                float4 ps[4] = {pa, pb, pc, pd};
#pragma unroll
                for (int q = 0; q < 4; q++) {
                    if (hs0[q] >= hth0) {
                        float d2 = fmaf(-2.0f, hs0[q], s0);
                        float w = __expf(FACT / fmaxf(d2, EPS) - m0);
                        sw0 += w;
                        ax0 = fmaf(w, ps[q].x, ax0);
                        ay0 = fmaf(w, ps[q].y, ay0);
                        az0 = fmaf(w, ps[q].z, az0);
                    }
                    if (hs1[q] >= hth1) {
                        float d2 = fmaf(-2.0f, hs1[q], s1);
                        float w = __expf(FACT / fmaxf(d2, EPS) - m1);
                        sw1 += w;
                        ax1 = fmaf(w, ps[q].x, ax1);
                        ay1 = fmaf(w, ps[q].y, ay1);
                        az1 = fmaf(w, ps[q].z, az1);
                    }
                }
            }
        }

        // Butterfly reductions (all lanes end with totals)
#pragma unroll
        for (int ofs = 16; ofs > 0; ofs >>= 1) {
            sw0 += __shfl_xor_sync(0xFFFFFFFFu, sw0, ofs);
            ax0 += __shfl_xor_sync(0xFFFFFFFFu, ax0, ofs);
            ay0 += __shfl_xor_sync(0xFFFFFFFFu, ay0, ofs);
            az0 += __shfl_xor_sync(0xFFFFFFFFu, az0, ofs);
            sw1 += __shfl_xor_sync(0xFFFFFFFFu, sw1, ofs);
            ax1 += __shfl_xor_sync(0xFFFFFFFFu, ax1, ofs);
            ay1 += __shfl_xor_sync(0xFFFFFFFFu, ay1, ofs);
            az1 += __shfl_xor_sync(0xFFFFFFFFu, az1, ofs);
        }

        if (lane < RW) {
            float sw = lane ? sw1 : sw0;
            float ax = lane ? ax1 : ax0;
            float ay = lane ? ay1 : ay0;
            float az = lane ? az1 : az0;
            float qx = lane ? x1 : x0;
            float qy = lane ? y1 : y0;
            float qz = lane ? z1 : z0;
            int i = row0 + lane;
            float inv = 1.0f / sw;
            float px = ax * inv, py = ay * inv, pz = az * inv;
            out[i] = px;
            out[N + i] = py;
            out[2 * N + i] = pz;
            float dx = qx - px + PD_EPS;
            float dy = qy - py + PD_EPS;
            float dz = qz - pz + PD_EPS;
            g_pd[i] = sqrtf(fmaf(dx, dx, fmaf(dy, dy, dz * dz)));
        }

        if (lane == 0) u = atomicAdd(&g_ctr, 1);
        u = __shfl_sync(0xFFFFFFFFu, u, 0);
    }
}

__global__ void mean_kernel(float* __restrict__ out, int out_size) {
    __shared__ float ss[32];
    const int tid = threadIdx.x;
    float acc = 0.f;
    for (int i = tid; i < N; i += 1024) acc += g_pd[i];
#pragma unroll
    for (int ofs = 16; ofs > 0; ofs >>= 1)
        acc += __shfl_xor_sync(0xFFFFFFFFu, acc, ofs);
    if ((tid & 31) == 0) ss[tid >> 5] = acc;
    __syncthreads();
    if (tid < 32) {
        float a = ss[tid];
#pragma unroll
        for (int ofs = 16; ofs > 0; ofs >>= 1)
            a += __shfl_xor_sync(0xFFFFFFFFu, a, ofs);
        if (tid == 0 && out_size > 3 * N) out[3 * N] = a * (1.0f / N);
    }
}

extern "C" void kernel_launch(void* const* d_in, const int* in_sizes, int n_in,
                              void* d_out, int out_size) {
    const float* pc1 = (const float*)d_in[0];
    const float* pc2 = (const float*)d_in[1];
    float* out = (float*)d_out;

    prep_kernel<<<(N + 255) / 256, 256>>>(pc2);
    soft_knn_kernel<<<CTAS, TPB>>>(pc1, out);
    mean_kernel<<<1, 1024>>>(out, out_size);
}